// round 2
// baseline (speedup 1.0000x reference)
#include <cuda_runtime.h>
#include <cuda_bf16.h>
#include <cstdint>

// ============================================================================
// Problem constants
// ============================================================================
#define B_ROWS   4096
#define N2       8192
#define DIM      512
#define BETA_INV 12.5f
#define EPS_F    1e-8f

// ============================================================================
// Scratch (device globals — no allocation allowed)
// ============================================================================
__device__ __align__(128) __nv_bfloat16 g_xnb[(size_t)N2 * DIM]; // bf16 normalized rows, 8 MB
__device__ float g_d[B_ROWS];     // exact f32 diagonal cosine x1n.x2n
__device__ float g_bm[N2];        // bias margins (row means of bias_map)
__device__ float g_rowsum[N2];    // sum_{j!=i} exp(c_ij/beta)
__device__ float g_rtot[4];
__device__ float g_rcnt[4];

// ============================================================================
// Helpers
// ============================================================================
__device__ __forceinline__ uint32_t smem_to_u32(const void* p) {
    uint32_t a;
    asm("{ .reg .u64 t; cvta.to.shared.u64 t, %1; cvt.u32.u64 %0, t; }" : "=r"(a) : "l"(p));
    return a;
}

#define SMEM_SWIZZLE_128B(byte_offset) ((byte_offset) ^ (((byte_offset) >> 3) & 0x70))

__device__ __forceinline__ void cp_async16(uint32_t smem_dst, const void* gmem_src) {
    asm volatile("cp.async.cg.shared.global [%0], [%1], 16;"
                 :: "r"(smem_dst), "l"(gmem_src) : "memory");
}
#define CP_ASYNC_COMMIT() asm volatile("cp.async.commit_group;" ::: "memory")
#define CP_ASYNC_WAIT(n)  asm volatile("cp.async.wait_group %0;" :: "n"(n) : "memory")

__device__ __forceinline__ void ldmatrix_x4(uint32_t& r0, uint32_t& r1,
                                            uint32_t& r2, uint32_t& r3, uint32_t addr) {
    asm volatile("ldmatrix.sync.aligned.m8n8.x4.shared.b16 {%0,%1,%2,%3}, [%4];"
                 : "=r"(r0), "=r"(r1), "=r"(r2), "=r"(r3) : "r"(addr));
}

__device__ __forceinline__ void mma16816(float* c, const uint32_t* a,
                                         uint32_t b0, uint32_t b1) {
    asm volatile(
        "mma.sync.aligned.m16n8k16.row.col.f32.bf16.bf16.f32 "
        "{%0,%1,%2,%3}, {%4,%5,%6,%7}, {%8,%9}, {%0,%1,%2,%3};"
        : "+f"(c[0]), "+f"(c[1]), "+f"(c[2]), "+f"(c[3])
        : "r"(a[0]), "r"(a[1]), "r"(a[2]), "r"(a[3]), "r"(b0), "r"(b1));
}

// ============================================================================
// Kernel 0: zero scratch accumulators (must run every graph replay)
// ============================================================================
__global__ void zero_kernel() {
    int i = blockIdx.x * 256 + threadIdx.x;
    if (i < N2) g_rowsum[i] = 0.0f;
    if (i < 4) { g_rtot[i] = 0.0f; g_rcnt[i] = 0.0f; }
}

// ============================================================================
// Kernel 1: per-row norms, exact f32 diagonal cosine, bf16 normalized rows
// grid = 4096 blocks x 128 threads (one block per row pair i)
// ============================================================================
__global__ void __launch_bounds__(128) prep_kernel(const float* __restrict__ x1,
                                                   const float* __restrict__ x2) {
    int i = blockIdx.x;
    int t = threadIdx.x;
    float4 a = reinterpret_cast<const float4*>(x1 + (size_t)i * DIM)[t];
    float4 c = reinterpret_cast<const float4*>(x2 + (size_t)i * DIM)[t];
    float n1 = a.x * a.x + a.y * a.y + a.z * a.z + a.w * a.w;
    float n2 = c.x * c.x + c.y * c.y + c.z * c.z + c.w * c.w;
    float dd = a.x * c.x + a.y * c.y + a.z * c.z + a.w * c.w;
#pragma unroll
    for (int o = 16; o > 0; o >>= 1) {
        n1 += __shfl_xor_sync(0xffffffffu, n1, o);
        n2 += __shfl_xor_sync(0xffffffffu, n2, o);
        dd += __shfl_xor_sync(0xffffffffu, dd, o);
    }
    __shared__ float s1[4], s2[4], sd[4];
    __shared__ float binv1, binv2;
    int w = t >> 5, l = t & 31;
    if (l == 0) { s1[w] = n1; s2[w] = n2; sd[w] = dd; }
    __syncthreads();
    if (t == 0) {
        float N1 = s1[0] + s1[1] + s1[2] + s1[3];
        float NN2 = s2[0] + s2[1] + s2[2] + s2[3];
        float DD = sd[0] + sd[1] + sd[2] + sd[3];
        float m1 = fmaxf(sqrtf(N1), EPS_F);
        float m2 = fmaxf(sqrtf(NN2), EPS_F);
        binv1 = 1.0f / m1;
        binv2 = 1.0f / m2;
        g_d[i] = DD / (m1 * m2);
    }
    __syncthreads();
    float i1 = binv1, i2 = binv2;
    __nv_bfloat162 h0 = __floats2bfloat162_rn(a.x * i1, a.y * i1);
    __nv_bfloat162 h1 = __floats2bfloat162_rn(a.z * i1, a.w * i1);
    uint2 u;
    u.x = *reinterpret_cast<uint32_t*>(&h0);
    u.y = *reinterpret_cast<uint32_t*>(&h1);
    reinterpret_cast<uint2*>(g_xnb + (size_t)i * DIM)[t] = u;
    h0 = __floats2bfloat162_rn(c.x * i2, c.y * i2);
    h1 = __floats2bfloat162_rn(c.z * i2, c.w * i2);
    u.x = *reinterpret_cast<uint32_t*>(&h0);
    u.y = *reinterpret_cast<uint32_t*>(&h1);
    reinterpret_cast<uint2*>(g_xnb + (size_t)(B_ROWS + i) * DIM)[t] = u;
}

// ============================================================================
// Kernel 2: bias margins (row means of bias_map) + race segment sums
// grid = 1024 blocks x 256 threads, one warp per row
// ============================================================================
__global__ void __launch_bounds__(256) bias_kernel(const float* __restrict__ bias_map,
                                                   const int* __restrict__ races) {
    __shared__ float st[4], sc[4];
    int tid = threadIdx.x;
    if (tid < 4) { st[tid] = 0.0f; sc[tid] = 0.0f; }
    __syncthreads();
    int w = tid >> 5, l = tid & 31;
    int row = blockIdx.x * 8 + w;
    float s = bias_map[(size_t)row * 64 + l] + bias_map[(size_t)row * 64 + 32 + l];
#pragma unroll
    for (int o = 16; o > 0; o >>= 1) s += __shfl_xor_sync(0xffffffffu, s, o);
    if (l == 0) {
        float mean = s * (1.0f / 64.0f);
        g_bm[row] = mean;
        int rc = races[row & (B_ROWS - 1)];
        atomicAdd(&st[rc], mean);
        atomicAdd(&sc[rc], 1.0f);
    }
    __syncthreads();
    if (tid < 4) {
        atomicAdd(&g_rtot[tid], st[tid]);
        atomicAdd(&g_rcnt[tid], sc[tid]);
    }
}

// ============================================================================
// Kernel 3: bf16 mma.sync GEMM (128x128 tile, K=512 in 8 double-buffered
// K=64 chunks via cp.async) + fused exp/rowsum epilogue, exact diagonal skip.
// 256 threads = 8 warps, 4(m) x 2(n); warp tile 32x64 = 2x8 m16n8k16 frags.
// SMEM: double-buffered A/B tiles, 128 rows x 128B (SW128 swizzle) each.
// ============================================================================
#define GEMM_SMEM_BYTES (4 * 16384 + 256)

__global__ void __launch_bounds__(256, 2) gemm_rowsum_kernel() {
    extern __shared__ char smem_raw[];
    uint32_t TILES = (smem_to_u32(smem_raw) + 127u) & ~127u;

    const int tid = threadIdx.x;
    const int wid = tid >> 5, lane = tid & 31;
    const int tn = blockIdx.x, tm = blockIdx.y;
    const int warp_m = wid & 3;        // 0..3 -> 32 rows each
    const int warp_n = wid >> 2;       // 0..1 -> 64 cols each
    const int group = lane >> 2;       // 0..7
    const int tq = lane & 3;           // 0..3

    const __nv_bfloat16* Arow = g_xnb + (size_t)tm * 128 * DIM;
    const __nv_bfloat16* Brow = g_xnb + (size_t)tn * 128 * DIM;

    // cp.async stage of one K=64 chunk into buffer b
    auto stage = [&](int kc, int b) {
        uint32_t abuf = TILES + (uint32_t)b * 32768u;
        uint32_t bbuf = abuf + 16384u;
#pragma unroll
        for (int it = 0; it < 4; it++) {
            int idx = tid + it * 256;     // 0..1023
            int r = idx >> 3;             // 0..127
            int c16 = idx & 7;            // 16B chunk
            uint32_t soff = SMEM_SWIZZLE_128B((uint32_t)(r * 128 + c16 * 16));
            cp_async16(abuf + soff, Arow + (size_t)r * DIM + kc * 64 + c16 * 8);
            cp_async16(bbuf + soff, Brow + (size_t)r * DIM + kc * 64 + c16 * 8);
        }
        CP_ASYNC_COMMIT();
    };

    float acc[2][8][4];
#pragma unroll
    for (int mf = 0; mf < 2; mf++)
#pragma unroll
        for (int nf = 0; nf < 8; nf++)
#pragma unroll
            for (int k = 0; k < 4; k++) acc[mf][nf][k] = 0.0f;

    stage(0, 0);

    const int ldm_row_a = warp_m * 32 + (lane & 15);
    const int ldm_row_b = warp_n * 64 + (lane & 15);
    const int ldm_colg = (lane >> 4) * 16;    // byte offset of 8-col group

    for (int kc = 0; kc < 8; kc++) {
        if (kc < 7) stage(kc + 1, (kc + 1) & 1);
        if (kc < 7) { CP_ASYNC_WAIT(1); } else { CP_ASYNC_WAIT(0); }
        __syncthreads();
        uint32_t abuf = TILES + (uint32_t)(kc & 1) * 32768u;
        uint32_t bbuf = abuf + 16384u;
#pragma unroll
        for (int ks = 0; ks < 4; ks++) {
            uint32_t a[2][4];
#pragma unroll
            for (int mf = 0; mf < 2; mf++) {
                uint32_t off = (uint32_t)((ldm_row_a + mf * 16) * 128 + ks * 32 + ldm_colg);
                ldmatrix_x4(a[mf][0], a[mf][1], a[mf][2], a[mf][3],
                            abuf + SMEM_SWIZZLE_128B(off));
            }
            uint32_t bfr[4][4];
#pragma unroll
            for (int nf2 = 0; nf2 < 4; nf2++) {
                uint32_t off = (uint32_t)((ldm_row_b + nf2 * 16) * 128 + ks * 32 + ldm_colg);
                ldmatrix_x4(bfr[nf2][0], bfr[nf2][1], bfr[nf2][2], bfr[nf2][3],
                            bbuf + SMEM_SWIZZLE_128B(off));
            }
#pragma unroll
            for (int mf = 0; mf < 2; mf++)
#pragma unroll
                for (int nf2 = 0; nf2 < 4; nf2++) {
                    mma16816(acc[mf][nf2 * 2 + 0], a[mf], bfr[nf2][0], bfr[nf2][2]);
                    mma16816(acc[mf][nf2 * 2 + 1], a[mf], bfr[nf2][1], bfr[nf2][3]);
                }
        }
        __syncthreads();
    }

    // Fused epilogue: exp(acc * 12.5), skip exact diagonal, reduce row sums.
    const int grow0 = tm * 128 + warp_m * 32 + group;   // + mf*16 (+8 for c2/c3)
    const int gcol0 = tn * 128 + warp_n * 64 + tq * 2;  // + nf*8 (+1 for odd)
#pragma unroll
    for (int mf = 0; mf < 2; mf++) {
        float s0 = 0.0f, s1 = 0.0f;
        int r0 = grow0 + mf * 16;
        int r1 = r0 + 8;
#pragma unroll
        for (int nf = 0; nf < 8; nf++) {
            int c0 = gcol0 + nf * 8;
            float e;
            e = __expf(acc[mf][nf][0] * BETA_INV); s0 += (c0     == r0) ? 0.0f : e;
            e = __expf(acc[mf][nf][1] * BETA_INV); s0 += (c0 + 1 == r0) ? 0.0f : e;
            e = __expf(acc[mf][nf][2] * BETA_INV); s1 += (c0     == r1) ? 0.0f : e;
            e = __expf(acc[mf][nf][3] * BETA_INV); s1 += (c0 + 1 == r1) ? 0.0f : e;
        }
        s0 += __shfl_xor_sync(0xffffffffu, s0, 1);
        s0 += __shfl_xor_sync(0xffffffffu, s0, 2);
        s1 += __shfl_xor_sync(0xffffffffu, s1, 1);
        s1 += __shfl_xor_sync(0xffffffffu, s1, 2);
        if (tq == 0) {
            atomicAdd(&g_rowsum[r0], s0);
            atomicAdd(&g_rowsum[r1], s1);
        }
    }
}

// ============================================================================
// Kernel 4: final loss + margins
// ============================================================================
__global__ void __launch_bounds__(256) finalize_kernel(float* out, int out_size) {
    int tid = threadIdx.x;
    float acc = 0.0f;
    for (int i = tid; i < N2; i += 256) {
        float dv = g_d[i & (B_ROWS - 1)];
        float bm = g_bm[i];
        float numlog = (dv - bm) * BETA_INV;
        float den = g_rowsum[i] - __expf(dv * BETA_INV) + __expf(numlog);
        acc += numlog - logf(den);
    }
#pragma unroll
    for (int o = 16; o > 0; o >>= 1) acc += __shfl_xor_sync(0xffffffffu, acc, o);
    __shared__ float sw[8];
    int w = tid >> 5, l = tid & 31;
    if (l == 0) sw[w] = acc;
    __syncthreads();
    if (tid == 0) {
        float tot = 0.0f;
#pragma unroll
        for (int k = 0; k < 8; k++) tot += sw[k];
        if (out_size > 0) out[0] = -tot / (float)N2;
    }
    if (tid >= 1 && tid < 5 && tid < out_size) {
        int r = tid - 1;
        out[tid] = (g_rcnt[r] > 0.0f) ? (g_rtot[r] / g_rcnt[r]) : 0.0f;
    }
    for (int k = 5 + tid; k < out_size; k += 256) out[k] = 0.0f;
}

// ============================================================================
// Launch
// ============================================================================
extern "C" void kernel_launch(void* const* d_in, const int* in_sizes, int n_in,
                              void* d_out, int out_size) {
    const float* x1       = (const float*)d_in[0];
    const float* x2       = (const float*)d_in[1];
    const int*   races    = (const int*)d_in[2];
    const float* bias_map = (const float*)d_in[3];
    float* out = (float*)d_out;

    cudaFuncSetAttribute(gemm_rowsum_kernel,
                         cudaFuncAttributeMaxDynamicSharedMemorySize, GEMM_SMEM_BYTES);

    zero_kernel<<<(N2 + 255) / 256, 256>>>();
    prep_kernel<<<B_ROWS, 128>>>(x1, x2);
    bias_kernel<<<N2 / 8, 256>>>(bias_map, races);
    gemm_rowsum_kernel<<<dim3(N2 / 128, N2 / 128), 256, GEMM_SMEM_BYTES>>>();
    finalize_kernel<<<1, 256>>>(out, out_size);
}

// round 3
// speedup vs baseline: 1.6492x; 1.6492x over previous
#include <cuda_runtime.h>
#include <cuda_bf16.h>
#include <cstdint>

// ============================================================================
// Problem constants
// ============================================================================
#define B_ROWS   4096
#define N2       8192
#define DIM      512
#define BETA_INV 12.5f
#define EPS_F    1e-8f
#define NTILE    64          // N2 / 128
#define NPAIRS   2080        // NTILE*(NTILE+1)/2 upper-triangular tiles

// ============================================================================
// Scratch (device globals — no allocation allowed)
// ============================================================================
__device__ __align__(128) __nv_bfloat16 g_xnb[(size_t)N2 * DIM]; // bf16 normalized rows, 8 MB
__device__ float g_d[B_ROWS];     // exact f32 diagonal cosine x1n.x2n
__device__ float g_bm[N2];        // bias margins (row means of bias_map)
__device__ float g_rowsum[N2];    // sum_{j!=i} exp(c_ij/beta)
__device__ float g_rtot[4];
__device__ float g_rcnt[4];

// ============================================================================
// Helpers
// ============================================================================
__device__ __forceinline__ uint32_t smem_to_u32(const void* p) {
    uint32_t a;
    asm("{ .reg .u64 t; cvta.to.shared.u64 t, %1; cvt.u32.u64 %0, t; }" : "=r"(a) : "l"(p));
    return a;
}

#define SMEM_SWIZZLE_128B(byte_offset) ((byte_offset) ^ (((byte_offset) >> 3) & 0x70))

__device__ __forceinline__ void cp_async16(uint32_t smem_dst, const void* gmem_src) {
    asm volatile("cp.async.cg.shared.global [%0], [%1], 16;"
                 :: "r"(smem_dst), "l"(gmem_src) : "memory");
}
#define CP_ASYNC_COMMIT() asm volatile("cp.async.commit_group;" ::: "memory")
#define CP_ASYNC_WAIT(n)  asm volatile("cp.async.wait_group %0;" :: "n"(n) : "memory")

__device__ __forceinline__ void ldmatrix_x4(uint32_t& r0, uint32_t& r1,
                                            uint32_t& r2, uint32_t& r3, uint32_t addr) {
    asm volatile("ldmatrix.sync.aligned.m8n8.x4.shared.b16 {%0,%1,%2,%3}, [%4];"
                 : "=r"(r0), "=r"(r1), "=r"(r2), "=r"(r3) : "r"(addr));
}

__device__ __forceinline__ void mma16816(float* c, const uint32_t* a,
                                         uint32_t b0, uint32_t b1) {
    asm volatile(
        "mma.sync.aligned.m16n8k16.row.col.f32.bf16.bf16.f32 "
        "{%0,%1,%2,%3}, {%4,%5,%6,%7}, {%8,%9}, {%0,%1,%2,%3};"
        : "+f"(c[0]), "+f"(c[1]), "+f"(c[2]), "+f"(c[3])
        : "r"(a[0]), "r"(a[1]), "r"(a[2]), "r"(a[3]), "r"(b0), "r"(b1));
}

// ============================================================================
// Kernel 0: zero scratch accumulators (must run every graph replay)
// ============================================================================
__global__ void zero_kernel() {
    int i = blockIdx.x * 256 + threadIdx.x;
    if (i < N2) g_rowsum[i] = 0.0f;
    if (i < 4) { g_rtot[i] = 0.0f; g_rcnt[i] = 0.0f; }
}

// ============================================================================
// Kernel 1: per-row norms, exact f32 diagonal cosine, bf16 normalized rows
// ============================================================================
__global__ void __launch_bounds__(128) prep_kernel(const float* __restrict__ x1,
                                                   const float* __restrict__ x2) {
    int i = blockIdx.x;
    int t = threadIdx.x;
    float4 a = reinterpret_cast<const float4*>(x1 + (size_t)i * DIM)[t];
    float4 c = reinterpret_cast<const float4*>(x2 + (size_t)i * DIM)[t];
    float n1 = a.x * a.x + a.y * a.y + a.z * a.z + a.w * a.w;
    float n2 = c.x * c.x + c.y * c.y + c.z * c.z + c.w * c.w;
    float dd = a.x * c.x + a.y * c.y + a.z * c.z + a.w * c.w;
#pragma unroll
    for (int o = 16; o > 0; o >>= 1) {
        n1 += __shfl_xor_sync(0xffffffffu, n1, o);
        n2 += __shfl_xor_sync(0xffffffffu, n2, o);
        dd += __shfl_xor_sync(0xffffffffu, dd, o);
    }
    __shared__ float s1[4], s2[4], sd[4];
    __shared__ float binv1, binv2;
    int w = t >> 5, l = t & 31;
    if (l == 0) { s1[w] = n1; s2[w] = n2; sd[w] = dd; }
    __syncthreads();
    if (t == 0) {
        float N1 = s1[0] + s1[1] + s1[2] + s1[3];
        float NN2 = s2[0] + s2[1] + s2[2] + s2[3];
        float DD = sd[0] + sd[1] + sd[2] + sd[3];
        float m1 = fmaxf(sqrtf(N1), EPS_F);
        float m2 = fmaxf(sqrtf(NN2), EPS_F);
        binv1 = 1.0f / m1;
        binv2 = 1.0f / m2;
        g_d[i] = DD / (m1 * m2);
    }
    __syncthreads();
    float i1 = binv1, i2 = binv2;
    __nv_bfloat162 h0 = __floats2bfloat162_rn(a.x * i1, a.y * i1);
    __nv_bfloat162 h1 = __floats2bfloat162_rn(a.z * i1, a.w * i1);
    uint2 u;
    u.x = *reinterpret_cast<uint32_t*>(&h0);
    u.y = *reinterpret_cast<uint32_t*>(&h1);
    reinterpret_cast<uint2*>(g_xnb + (size_t)i * DIM)[t] = u;
    h0 = __floats2bfloat162_rn(c.x * i2, c.y * i2);
    h1 = __floats2bfloat162_rn(c.z * i2, c.w * i2);
    u.x = *reinterpret_cast<uint32_t*>(&h0);
    u.y = *reinterpret_cast<uint32_t*>(&h1);
    reinterpret_cast<uint2*>(g_xnb + (size_t)(B_ROWS + i) * DIM)[t] = u;
}

// ============================================================================
// Kernel 2: bias margins (row means of bias_map) + race segment sums
// ============================================================================
__global__ void __launch_bounds__(256) bias_kernel(const float* __restrict__ bias_map,
                                                   const int* __restrict__ races) {
    __shared__ float st[4], sc[4];
    int tid = threadIdx.x;
    if (tid < 4) { st[tid] = 0.0f; sc[tid] = 0.0f; }
    __syncthreads();
    int w = tid >> 5, l = tid & 31;
    int row = blockIdx.x * 8 + w;
    float s = bias_map[(size_t)row * 64 + l] + bias_map[(size_t)row * 64 + 32 + l];
#pragma unroll
    for (int o = 16; o > 0; o >>= 1) s += __shfl_xor_sync(0xffffffffu, s, o);
    if (l == 0) {
        float mean = s * (1.0f / 64.0f);
        g_bm[row] = mean;
        int rc = races[row & (B_ROWS - 1)];
        atomicAdd(&st[rc], mean);
        atomicAdd(&sc[rc], 1.0f);
    }
    __syncthreads();
    if (tid < 4) {
        atomicAdd(&g_rtot[tid], st[tid]);
        atomicAdd(&g_rcnt[tid], sc[tid]);
    }
}

// ============================================================================
// Kernel 3: SYMMETRIC bf16 mma.sync GEMM over upper-triangular 128x128 tiles.
// Each off-diagonal tile feeds BOTH row sums (rows tm*128..) and, via the
// symmetric transpose, rows tn*128.. (as column sums of the tile).
// 256 threads = 8 warps, 4(m) x 2(n); warp tile 32x64 = 2x8 m16n8k16 frags.
// K=512 in 8 double-buffered K=64 chunks via cp.async, SW128 SMEM.
// ============================================================================
#define GEMM_SMEM_BYTES (4 * 16384 + 256)

__global__ void __launch_bounds__(256, 2) gemm_rowsum_sym_kernel() {
    extern __shared__ char smem_raw[];
    uint32_t TILES = (smem_to_u32(smem_raw) + 127u) & ~127u;

    // Map linear block id -> (tm, tn), tm <= tn (row-major upper triangle)
    int t = blockIdx.x;
    int tm = 0, rem = t;
    while (rem >= NTILE - tm) { rem -= NTILE - tm; tm++; }
    const int tn = tm + rem;
    const bool diag = (tm == tn);

    const int tid = threadIdx.x;
    const int wid = tid >> 5, lane = tid & 31;
    const int warp_m = wid & 3;        // 0..3 -> 32 rows each
    const int warp_n = wid >> 2;       // 0..1 -> 64 cols each
    const int group = lane >> 2;       // 0..7
    const int tq = lane & 3;           // 0..3

    const __nv_bfloat16* Arow = g_xnb + (size_t)tm * 128 * DIM;
    const __nv_bfloat16* Brow = g_xnb + (size_t)tn * 128 * DIM;

    auto stage = [&](int kc, int b) {
        uint32_t abuf = TILES + (uint32_t)b * 32768u;
        uint32_t bbuf = abuf + 16384u;
#pragma unroll
        for (int it = 0; it < 4; it++) {
            int idx = tid + it * 256;     // 0..1023
            int r = idx >> 3;             // 0..127
            int c16 = idx & 7;            // 16B chunk
            uint32_t soff = SMEM_SWIZZLE_128B((uint32_t)(r * 128 + c16 * 16));
            cp_async16(abuf + soff, Arow + (size_t)r * DIM + kc * 64 + c16 * 8);
            cp_async16(bbuf + soff, Brow + (size_t)r * DIM + kc * 64 + c16 * 8);
        }
        CP_ASYNC_COMMIT();
    };

    float acc[2][8][4];
#pragma unroll
    for (int mf = 0; mf < 2; mf++)
#pragma unroll
        for (int nf = 0; nf < 8; nf++)
#pragma unroll
            for (int k = 0; k < 4; k++) acc[mf][nf][k] = 0.0f;

    stage(0, 0);

    const int ldm_row_a = warp_m * 32 + (lane & 15);
    const int ldm_row_b = warp_n * 64 + (lane & 15);
    const int ldm_colg = (lane >> 4) * 16;    // byte offset of 8-col group

    for (int kc = 0; kc < 8; kc++) {
        CP_ASYNC_WAIT(0);                 // chunk kc resident
        __syncthreads();                  // all warps done with previous buffer
        if (kc < 7) stage(kc + 1, (kc + 1) & 1);   // prefetch into other buffer
        uint32_t abuf = TILES + (uint32_t)(kc & 1) * 32768u;
        uint32_t bbuf = abuf + 16384u;
#pragma unroll
        for (int ks = 0; ks < 4; ks++) {
            uint32_t a[2][4];
#pragma unroll
            for (int mf = 0; mf < 2; mf++) {
                uint32_t off = (uint32_t)((ldm_row_a + mf * 16) * 128 + ks * 32 + ldm_colg);
                ldmatrix_x4(a[mf][0], a[mf][1], a[mf][2], a[mf][3],
                            abuf + SMEM_SWIZZLE_128B(off));
            }
            uint32_t bfr[4][4];
#pragma unroll
            for (int nf2 = 0; nf2 < 4; nf2++) {
                uint32_t off = (uint32_t)((ldm_row_b + nf2 * 16) * 128 + ks * 32 + ldm_colg);
                ldmatrix_x4(bfr[nf2][0], bfr[nf2][1], bfr[nf2][2], bfr[nf2][3],
                            bbuf + SMEM_SWIZZLE_128B(off));
            }
#pragma unroll
            for (int mf = 0; mf < 2; mf++)
#pragma unroll
                for (int nf2 = 0; nf2 < 4; nf2++) {
                    mma16816(acc[mf][nf2 * 2 + 0], a[mf], bfr[nf2][0], bfr[nf2][2]);
                    mma16816(acc[mf][nf2 * 2 + 1], a[mf], bfr[nf2][1], bfr[nf2][3]);
                }
        }
    }

    // ------------------------------------------------------------------
    // Epilogue. exp(acc*12.5); rows -> rowsum[tm block]; for off-diagonal
    // tiles, column sums -> rowsum[tn block] (symmetry). Diagonal tiles
    // skip the exact diagonal element and take only the row path.
    // ------------------------------------------------------------------
    const int grow0 = tm * 128 + warp_m * 32 + group;   // + mf*16 (+8 for k=2,3)
    const int gcol0 = tn * 128 + warp_n * 64 + tq * 2;  // + nf*8 (+1 for odd)

    float cs[8][2];
#pragma unroll
    for (int nf = 0; nf < 8; nf++) { cs[nf][0] = 0.0f; cs[nf][1] = 0.0f; }

#pragma unroll
    for (int mf = 0; mf < 2; mf++) {
        float s0 = 0.0f, s1 = 0.0f;
        int r0 = grow0 + mf * 16;
        int r1 = r0 + 8;
#pragma unroll
        for (int nf = 0; nf < 8; nf++) {
            int c0 = gcol0 + nf * 8;
            float e00 = __expf(acc[mf][nf][0] * BETA_INV);
            float e01 = __expf(acc[mf][nf][1] * BETA_INV);
            float e10 = __expf(acc[mf][nf][2] * BETA_INV);
            float e11 = __expf(acc[mf][nf][3] * BETA_INV);
            if (diag) {
                if (c0 == r0)     e00 = 0.0f;
                if (c0 + 1 == r0) e01 = 0.0f;
                if (c0 == r1)     e10 = 0.0f;
                if (c0 + 1 == r1) e11 = 0.0f;
            }
            s0 += e00 + e01;
            s1 += e10 + e11;
            cs[nf][0] += e00 + e10;
            cs[nf][1] += e01 + e11;
        }
        s0 += __shfl_xor_sync(0xffffffffu, s0, 1);
        s0 += __shfl_xor_sync(0xffffffffu, s0, 2);
        s1 += __shfl_xor_sync(0xffffffffu, s1, 1);
        s1 += __shfl_xor_sync(0xffffffffu, s1, 2);
        if (tq == 0) {
            atomicAdd(&g_rowsum[r0], s0);
            atomicAdd(&g_rowsum[r1], s1);
        }
    }

    if (!diag) {
        // Column sums: reduce over the 16 rows this warp covers per column
        // (butterfly across group bits), then one atomic per column.
#pragma unroll
        for (int nf = 0; nf < 8; nf++) {
#pragma unroll
            for (int p = 0; p < 2; p++) {
                float v = cs[nf][p];
                v += __shfl_xor_sync(0xffffffffu, v, 4);
                v += __shfl_xor_sync(0xffffffffu, v, 8);
                v += __shfl_xor_sync(0xffffffffu, v, 16);
                if (lane < 4) {   // lane == tq representative
                    atomicAdd(&g_rowsum[gcol0 + nf * 8 + p], v);
                }
            }
        }
    }
}

// ============================================================================
// Kernel 4: final loss + margins
// ============================================================================
__global__ void __launch_bounds__(256) finalize_kernel(float* out, int out_size) {
    int tid = threadIdx.x;
    float acc = 0.0f;
    for (int i = tid; i < N2; i += 256) {
        float dv = g_d[i & (B_ROWS - 1)];
        float bm = g_bm[i];
        float numlog = (dv - bm) * BETA_INV;
        float den = g_rowsum[i] - __expf(dv * BETA_INV) + __expf(numlog);
        acc += numlog - logf(den);
    }
#pragma unroll
    for (int o = 16; o > 0; o >>= 1) acc += __shfl_xor_sync(0xffffffffu, acc, o);
    __shared__ float sw[8];
    int w = tid >> 5, l = tid & 31;
    if (l == 0) sw[w] = acc;
    __syncthreads();
    if (tid == 0) {
        float tot = 0.0f;
#pragma unroll
        for (int k = 0; k < 8; k++) tot += sw[k];
        if (out_size > 0) out[0] = -tot / (float)N2;
    }
    if (tid >= 1 && tid < 5 && tid < out_size) {
        int r = tid - 1;
        out[tid] = (g_rcnt[r] > 0.0f) ? (g_rtot[r] / g_rcnt[r]) : 0.0f;
    }
    for (int k = 5 + tid; k < out_size; k += 256) out[k] = 0.0f;
}

// ============================================================================
// Launch
// ============================================================================
extern "C" void kernel_launch(void* const* d_in, const int* in_sizes, int n_in,
                              void* d_out, int out_size) {
    const float* x1       = (const float*)d_in[0];
    const float* x2       = (const float*)d_in[1];
    const int*   races    = (const int*)d_in[2];
    const float* bias_map = (const float*)d_in[3];
    float* out = (float*)d_out;

    cudaFuncSetAttribute(gemm_rowsum_sym_kernel,
                         cudaFuncAttributeMaxDynamicSharedMemorySize, GEMM_SMEM_BYTES);

    zero_kernel<<<(N2 + 255) / 256, 256>>>();
    prep_kernel<<<B_ROWS, 128>>>(x1, x2);
    bias_kernel<<<N2 / 8, 256>>>(bias_map, races);
    gemm_rowsum_sym_kernel<<<NPAIRS, 256, GEMM_SMEM_BYTES>>>();
    finalize_kernel<<<1, 256>>>(out, out_size);
}